// round 2
// baseline (speedup 1.0000x reference)
#include <cuda_runtime.h>
#include <cstdint>

// ScatterEdges: out[src[e]] += x[e]*switch[e]; out[dst[e]] += x[e]*switch[e]
// E = 3.2M edges, D = 64 feats (256B rows), N = 100K nodes.
//
// Strategy: stage scaled edge rows in SMEM, then push the scatter-add through
// the TMA bulk-reduce engine (cp.reduce.async.bulk -> UBLKRED). This removes
// the per-lane RED.128 wavefronts from the L1tex/LSU pipe, which round-1 ncu
// showed to be the binding resource (L1=79%, L2=65%, DRAM=37%).

#define D_FEAT 64
#define CHUNKS 16                 // float4 chunks per 256B row
#define EDGES_PER_BATCH 64
#define THREADS 256
#define FILL_PASSES (EDGES_PER_BATCH * CHUNKS / THREADS)   // 4
#define ROW_BYTES 256

__global__ void zero_out_kernel(float4* __restrict__ out4, int n4) {
    int i = blockIdx.x * blockDim.x + threadIdx.x;
    int stride = gridDim.x * blockDim.x;
    for (; i < n4; i += stride) {
        out4[i] = make_float4(0.f, 0.f, 0.f, 0.f);
    }
}

__global__ void __launch_bounds__(THREADS)
scatter_tma_kernel(const float4* __restrict__ x4,
                   const float* __restrict__ sw,
                   const int* __restrict__ src,
                   const int* __restrict__ dst,
                   float* __restrict__ out,
                   int n_edges) {
    // Double-buffered staging: 2 x 64 rows x 256B = 32KB static smem.
    __shared__ __align__(256) float4 buf[2][EDGES_PER_BATCH][CHUNKS];

    int t = threadIdx.x;
    int n_batches = (n_edges + EDGES_PER_BATCH - 1) / EDGES_PER_BATCH;

    int it = 0;
    for (int b = blockIdx.x; b < n_batches; b += gridDim.x, ++it) {
        int bi = it & 1;

        // Reuse safety: buffer `bi` was last handed to TMA 2 iterations ago.
        // wait_group 1 leaves at most the previous iteration's group pending.
        asm volatile("cp.async.bulk.wait_group 1;" ::: "memory");
        __syncthreads();

        // ---- fill: scale x rows into smem (coalesced LDG.128 / STS.128) ----
        int e0 = b * EDGES_PER_BATCH;
        #pragma unroll
        for (int p = 0; p < FILL_PASSES; p++) {
            int el    = p * (THREADS / CHUNKS) + (t >> 4);  // local edge 0..63
            int chunk = t & (CHUNKS - 1);
            int e = e0 + el;
            if (e < n_edges) {
                float s = __ldg(&sw[e]);
                float4 v = __ldg(&x4[(size_t)e * CHUNKS + chunk]);
                v.x *= s; v.y *= s; v.z *= s; v.w *= s;
                buf[bi][el][chunk] = v;
            }
        }
        __syncthreads();
        // Generic smem writes must be visible to the async proxy before TMA reads.
        asm volatile("fence.proxy.async.shared::cta;" ::: "memory");

        // ---- issue: one 256B bulk-reduce per edge-endpoint (threads 0..127) ----
        if (t < 2 * EDGES_PER_BATCH) {
            int el = t >> 1;
            int e  = e0 + el;
            if (e < n_edges) {
                int node = (t & 1) ? __ldg(&dst[e]) : __ldg(&src[e]);
                float* gdst = out + (size_t)node * D_FEAT;
                uint32_t saddr =
                    (uint32_t)__cvta_generic_to_shared(&buf[bi][el][0]);
                asm volatile(
                    "cp.reduce.async.bulk.global.shared::cta.bulk_group.add.f32 "
                    "[%0], [%1], %2;"
                    :: "l"(gdst), "r"(saddr), "r"(ROW_BYTES) : "memory");
            }
        }
        asm volatile("cp.async.bulk.commit_group;" ::: "memory");
    }

    // Drain all outstanding bulk-reduces before exit.
    asm volatile("cp.async.bulk.wait_group 0;" ::: "memory");
}

extern "C" void kernel_launch(void* const* d_in, const int* in_sizes, int n_in,
                              void* d_out, int out_size) {
    // metadata order: x [E*64], switch [E], edge_src [E], edge_dst [E], species [N]
    const float4* x4  = (const float4*)d_in[0];
    const float*  sw  = (const float*)d_in[1];
    const int*    src = (const int*)d_in[2];
    const int*    dst = (const int*)d_in[3];
    float* out = (float*)d_out;

    int n_edges = in_sizes[1];   // switch has E elements

    // Zero the (poisoned) output first.
    int n4 = out_size / 4;
    int zblocks = (n4 + 255) / 256;
    if (zblocks > 8192) zblocks = 8192;
    zero_out_kernel<<<zblocks, 256>>>((float4*)out, n4);

    int n_batches = (n_edges + EDGES_PER_BATCH - 1) / EDGES_PER_BATCH;
    int grid = 148 * 7;                 // ~7 CTAs/SM at 32KB smem, 256 thr
    if (grid > n_batches) grid = n_batches;
    scatter_tma_kernel<<<grid, THREADS>>>(x4, sw, src, dst, out, n_edges);
}